// round 1
// baseline (speedup 1.0000x reference)
#include <cuda_runtime.h>

#define T_DIM 512
#define Q_DIM 4
#define N_STEPS 5

__device__ __forceinline__ float sgnf(float x) {
    return (x > 0.0f) ? 1.0f : ((x < 0.0f) ? -1.0f : 0.0f);
}

__device__ __forceinline__ float rescale_f(float x) {
    const float EPS = 1e-3f;
    return sgnf(x) * (sqrtf(fabsf(x) + 1.0f) - 1.0f) + EPS * x;
}

__device__ __forceinline__ float inv_rescale_f(float x) {
    const float EPS = 1e-3f;
    float sqrt_arg = 1.0f + 4.0f * EPS * (fabsf(x) + 1.0f + EPS);
    float r = (sqrtf(sqrt_arg) - 1.0f) / (2.0f * EPS);
    return sgnf(x) * (r * r - 1.0f);
}

__global__ __launch_bounds__(T_DIM)
void nstep_qloss_kernel(const float* __restrict__ cq,
                        const float* __restrict__ nq,
                        const float* __restrict__ logp,
                        const float* __restrict__ rw,
                        const float* __restrict__ done,
                        const float* __restrict__ mask,
                        float* __restrict__ out)
{
    __shared__ float4 s_mr[T_DIM];   // mask * reward
    __shared__ float4 s_nq[T_DIM];   // m*(1-d) * inv_rescale(next_q)
    __shared__ float  s_lp[T_DIM];   // (1/3) * m*(1-d) * log_p

    const float GAMMA = 0.997f;
    const float LN_GAMMA = -0.003004509021390342f; // ln(0.997)

    int b = blockIdx.x;
    int t = threadIdx.x;
    long bt = (long)b * T_DIM + t;

    float m = mask[bt];
    float d = done[bt];
    float md = m * (1.0f - d);

    s_lp[t] = (1.0f / 3.0f) * md * logp[bt];

    float4 r4 = ((const float4*)rw)[bt];
    s_mr[t] = make_float4(m * r4.x, m * r4.y, m * r4.z, m * r4.w);

    float4 n4 = ((const float4*)nq)[bt];
    s_nq[t] = make_float4(md * inv_rescale_f(n4.x),
                          md * inv_rescale_f(n4.y),
                          md * inv_rescale_f(n4.z),
                          md * inv_rescale_f(n4.w));
    __syncthreads();

    // windowed sums over n = 0..4
    float rs0 = 0.f, rs1 = 0.f, rs2 = 0.f, rs3 = 0.f;
    float lps = 0.f;   // sum gamma^(n+1) * lp[t+n]
    float g = 1.0f;
    #pragma unroll
    for (int n = 0; n < N_STEPS; n++) {
        int tn = t + n;
        if (tn < T_DIM) {
            float4 v = s_mr[tn];
            rs0 += g * v.x;
            rs1 += g * v.y;
            rs2 += g * v.z;
            rs3 += g * v.w;
            lps += g * GAMMA * s_lp[tn];
        }
        g *= GAMMA;
    }

    int idx = min(T_DIM - 1, t + N_STEPS - 1);
    float gi = expf((float)idx * LN_GAMMA);   // gamma^idx (absolute index, per reference)
    float4 nv = s_nq[idx];

    float4 c4 = ((const float4*)cq)[bt];

    // Q_WEIGHTS = [1, 0.5, 0, 2]; inv_qw = [1, 2, 0, 0.5]
    float t0 = rescale_f(rs0 + gi * nv.x + lps * 1.0f);
    float t1 = rescale_f(rs1 + gi * nv.y + lps * 2.0f);
    float t2 = rescale_f(rs2 + gi * nv.z + lps * 0.0f);
    float t3 = rescale_f(rs3 + gi * nv.w + lps * 0.5f);

    float e0 = c4.x - t0;
    float e1 = c4.y - t1;
    float e2 = c4.z - t2;
    float e3 = c4.w - t3;

    float4 o;
    o.x = 0.5f * m * 1.0f * e0 * e0;
    o.y = 0.5f * m * 0.5f * e1 * e1;
    o.z = 0.0f * e2;                    // q_w = 0 -> exactly 0 (m, finite e2)
    o.w = 0.5f * m * 2.0f * e3 * e3;

    ((float4*)out)[bt] = o;
}

extern "C" void kernel_launch(void* const* d_in, const int* in_sizes, int n_in,
                              void* d_out, int out_size)
{
    // metadata order: current_q_value, next_q_value, log_p, reward, is_done, mask
    const float* cq   = (const float*)d_in[0];
    const float* nq   = (const float*)d_in[1];
    const float* logp = (const float*)d_in[2];
    const float* rw   = (const float*)d_in[3];
    const float* done = (const float*)d_in[4];
    const float* mask = (const float*)d_in[5];
    float* out = (float*)d_out;

    int B = in_sizes[2] / T_DIM;   // log_p has B*T elements
    nstep_qloss_kernel<<<B, T_DIM>>>(cq, nq, logp, rw, done, mask, out);
}